// round 6
// baseline (speedup 1.0000x reference)
#include <cuda_runtime.h>
#include <cuda_bf16.h>
#include <cstdint>

#define IMG_N_ANC   8649      // 31*31*9
#define SORT_N      16384
#define SEL_N       8192
#define PRE_NMS     6000
#define POST_NMS    1500
#define IOU_THR     0.7f
#define BATCH       16
#define NW          94        // 94 u64 words cover 6016 >= 6000 cols
#define NWP         96        // padded row stride (768 B)
#define NPAD        6016
#define NBIN        2048

typedef unsigned long long u64;

// ---------------- device scratch (static; no allocations) ----------------
// row-major masks: g_masks[b][row][word]  (word w holds cols w*64..w*64+63)
__device__ u64   g_masks[BATCH][NPAD][NWP];   // ~73.9 MB
__device__ float g_y1[BATCH][NPAD];
__device__ float g_x1[BATCH][NPAD];
__device__ float g_y2[BATCH][NPAD];
__device__ float g_x2[BATCH][NPAD];
__device__ float g_ar[BATCH][NPAD];
__device__ float g_sc[BATCH][NPAD];

// ---------- descending bitonic sort, register-tiled (tile = 8 keys) --------
__device__ __forceinline__ void bitonic_sort_desc(u64* keys, int n, int tid, int nt)
{
    const int tiles = n >> 3;

    // mega pass: k = 2,4,8 entirely inside each 8-key tile (no barriers)
    for (int t = tid; t < tiles; t += nt) {
        const int base = t << 3;
        u64 r[8];
        #pragma unroll
        for (int e = 0; e < 8; e++) r[e] = keys[base + e];
        #pragma unroll
        for (int k = 2; k <= 8; k <<= 1) {
            #pragma unroll
            for (int j = k >> 1; j > 0; j >>= 1) {
                #pragma unroll
                for (int e = 0; e < 8; e++) {
                    if (!(e & j)) {
                        bool dir = (((base + e) & k) == 0);
                        u64 a = r[e], c = r[e | j];
                        if ((a < c) == dir) { r[e] = c; r[e | j] = a; }
                    }
                }
            }
        }
        #pragma unroll
        for (int e = 0; e < 8; e++) keys[base + e] = r[e];
    }
    __syncthreads();

    for (int k = 16; k <= n; k <<= 1) {
        for (int j = k >> 1; j >= 8; j >>= 1) {
            const int half = n >> 1;
            for (int p = tid; p < half; p += nt) {
                int i  = ((p & ~(j - 1)) << 1) | (p & (j - 1));
                int ix = i + j;
                u64 a = keys[i], c = keys[ix];
                bool dir = ((i & k) == 0);
                if ((a < c) == dir) { keys[i] = c; keys[ix] = a; }
            }
            __syncthreads();
        }
        for (int t = tid; t < tiles; t += nt) {
            const int base = t << 3;
            const bool dir = ((base & k) == 0);
            u64 r[8];
            #pragma unroll
            for (int e = 0; e < 8; e++) r[e] = keys[base + e];
            #pragma unroll
            for (int j = 4; j > 0; j >>= 1) {
                #pragma unroll
                for (int e = 0; e < 8; e++) {
                    if (!(e & j)) {
                        u64 a = r[e], c = r[e | j];
                        if ((a < c) == dir) { r[e] = c; r[e | j] = a; }
                    }
                }
            }
            #pragma unroll
            for (int e = 0; e < 8; e++) keys[base + e] = r[e];
        }
        __syncthreads();
    }
}

// ================= Kernel A: select + sort + decode top-6000 =================
#define A_OFF_KSORT   (SORT_N * 8)                 // 131072
#define A_OFF_HIST    (A_OFF_KSORT + SEL_N * 8)    // 196608
#define A_OFF_CTL     (A_OFF_HIST + NBIN * 4)      // 204800
#define A_SMEM_TOTAL  (A_OFF_CTL + 16)
#define A_NT          1024

__global__ __launch_bounds__(A_NT, 1)
void sort_decode_kernel(const float* __restrict__ deltas,   // [B,N,4]
                        const float* __restrict__ probs,    // [B,N]
                        const float* __restrict__ anchors)  // [N,4]
{
    extern __shared__ char smem[];
    u64* keys_in   = (u64*)smem;
    u64* keys_sort = (u64*)(smem + A_OFF_KSORT);
    unsigned int* hist = (unsigned int*)(smem + A_OFF_HIST);
    int* s_bint  = (int*)(smem + A_OFF_CTL);
    int* s_total = (int*)(smem + A_OFF_CTL + 4);
    int* s_cnt   = (int*)(smem + A_OFF_CTL + 8);

    const int b   = blockIdx.x;
    const int tid = threadIdx.x;
    const int nt  = A_NT;

    for (int i = tid; i < NBIN; i += nt) hist[i] = 0u;
    if (tid == 0) *s_cnt = 0;
    __syncthreads();

    const float* pb = probs + (size_t)b * IMG_N_ANC;
    for (int i = tid; i < SORT_N; i += nt) {
        u64 k = 0ull;
        if (i < IMG_N_ANC) {
            unsigned int bits = __float_as_uint(pb[i]);  // [0,1): bit order == value order
            k = ((u64)bits << 32) | (u64)(0xFFFFFFFFu - (unsigned)i);
            atomicAdd(&hist[(unsigned)(k >> 51)], 1u);
        }
        keys_in[i] = k;
    }
    __syncthreads();

    if (tid < 32) {
        const int lane = tid;
        int part = 0;
        #pragma unroll 8
        for (int q = 0; q < 64; q++) part += (int)hist[NBIN - 1 - (lane * 64 + q)];
        int inc = part;
        #pragma unroll
        for (int off = 1; off < 32; off <<= 1) {
            int v = __shfl_up_sync(0xFFFFFFFFu, inc, off);
            if (lane >= off) inc += v;
        }
        int run = inc - part;   // exclusive
        for (int q = 0; q < 64; q++) {
            int v = NBIN - 1 - (lane * 64 + q);
            int h = (int)hist[v];
            run += h;
            if (run >= PRE_NMS && run - h < PRE_NMS) { *s_bint = v; *s_total = run; }
        }
    }
    __syncthreads();

    const int bint  = *s_bint;
    const int total = *s_total;
    const bool mainpath = (total <= SEL_N);

    if (mainpath) {
        for (int i = tid; i < IMG_N_ANC; i += nt) {
            u64 k = keys_in[i];
            if ((int)(unsigned)(k >> 51) >= bint) {
                int pos = atomicAdd(s_cnt, 1);
                keys_sort[pos] = k;
            }
        }
        for (int i = total + tid; i < SEL_N; i += nt) keys_sort[i] = 0ull;
        __syncthreads();
        bitonic_sort_desc(keys_sort, SEL_N, tid, nt);
    } else {
        bitonic_sort_desc(keys_in, SORT_N, tid, nt);   // fallback (never expected)
    }

    const u64* sorted = mainpath ? keys_sort : keys_in;

    const float* db = deltas + (size_t)b * IMG_N_ANC * 4;
    for (int t = tid; t < PRE_NMS; t += nt) {
        u64 key = sorted[t];
        unsigned int idx = 0xFFFFFFFFu - (unsigned int)(key & 0xFFFFFFFFull);
        float score = __uint_as_float((unsigned int)(key >> 32));

        float a0 = anchors[idx * 4 + 0];
        float a1 = anchors[idx * 4 + 1];
        float a2 = anchors[idx * 4 + 2];
        float a3 = anchors[idx * 4 + 3];
        float d0 = db[(size_t)idx * 4 + 0] * 0.1f;
        float d1 = db[(size_t)idx * 4 + 1] * 0.1f;
        float d2 = db[(size_t)idx * 4 + 2] * 0.2f;
        float d3 = db[(size_t)idx * 4 + 3] * 0.2f;

        float anc_h = a2 - a0;
        float anc_w = a3 - a1;
        float ctr_y = a0 + 0.5f * anc_h;
        float ctr_x = a1 + 0.5f * anc_w;
        float bh = expf(d2) * anc_h;
        float bw = expf(d3) * anc_w;
        float bcy = d0 * anc_h + ctr_y;
        float bcx = d1 * anc_w + ctr_x;
        float y1 = bcy - 0.5f * bh;
        float x1 = bcx - 0.5f * bw;
        float y2 = y1 + bh;
        float x2 = x1 + bw;

        g_y1[b][t] = y1; g_x1[b][t] = x1;
        g_y2[b][t] = y2; g_x2[b][t] = x2;
        g_ar[b][t] = (y2 - y1) * (x2 - x1);
        g_sc[b][t] = score;
    }
}

// ================= Kernel B: forward suppression bit-matrix (supertile) =====
// grid = (24 col_supertiles, 24 row_supertiles, 16 batches), 128 threads.
// Block covers 256 rows x 256 cols; column tile loaded once into smem and
// reused for 4 mask words. Each thread owns 2 rows.
#define B_NT    128
#define B_COLS  256
#define B_ROWS  256
#define B_SB    24
#define B_BAND  1e-4f

__global__ __launch_bounds__(B_NT)
void iou_matrix_kernel()
{
    const int csb = blockIdx.x;
    const int rsb = blockIdx.y;
    if (csb < rsb) return;                 // need cols >= rows only
    const int b   = blockIdx.z;
    const int tid = threadIdx.x;

    __shared__ float4 cbox[B_COLS];
    __shared__ float  care[B_COLS];

    const int c0 = csb * B_COLS;
    for (int cc = tid; cc < B_COLS; cc += B_NT) {
        int j = c0 + cc;
        if (j < PRE_NMS) {
            cbox[cc] = make_float4(g_y1[b][j], g_x1[b][j], g_y2[b][j], g_x2[b][j]);
            care[cc] = g_ar[b][j];
        } else {
            cbox[cc] = make_float4(0.f, 0.f, 0.f, 0.f);   // inter=0 -> definite miss
            care[cc] = 0.f;
        }
    }
    __syncthreads();

    float ry1[2], rx1[2], ry2[2], rx2[2], rar[2];
    int   irow[2];
    #pragma unroll
    for (int r = 0; r < 2; r++) {
        int i = rsb * B_ROWS + r * B_NT + tid;
        irow[r] = i;
        int ii = (i < PRE_NMS) ? i : 0;
        ry1[r] = g_y1[b][ii]; rx1[r] = g_x1[b][ii];
        ry2[r] = g_y2[b][ii]; rx2[r] = g_x2[b][ii];
        rar[r] = g_ar[b][ii];
    }

    #pragma unroll
    for (int w = 0; w < 4; w++) {
        const int wg = csb * 4 + w;        // global word index
        u64 bits[2] = {0ull, 0ull};
        u64 fall[2] = {0ull, 0ull};

        #pragma unroll 4
        for (int j = 0; j < 64; j++) {
            float4 c4 = cbox[w * 64 + j];
            float  ca = care[w * 64 + j];
            #pragma unroll
            for (int r = 0; r < 2; r++) {
                float ih = fmaxf(fminf(ry2[r], c4.z) - fmaxf(ry1[r], c4.x), 0.0f);
                float iw = fmaxf(fminf(rx2[r], c4.w) - fmaxf(rx1[r], c4.y), 0.0f);
                float inter = ih * iw;
                float d = (rar[r] + ca) - inter;         // fast denom (no +1e-8)
                float diff = fmaf(-IOU_THR, d, inter);   // inter - 0.7*d
                if (diff > 0.0f)                bits[r] |= (1ull << j);
                if (fabsf(diff) <= B_BAND * d)  fall[r] |= (1ull << j);
            }
        }

        // rare: resolve in-band pairs with the exact reference arithmetic
        #pragma unroll
        for (int r = 0; r < 2; r++) {
            u64 f = fall[r];
            while (f) {
                int j = __ffsll((long long)f) - 1;
                f &= f - 1ull;
                float4 c4 = cbox[w * 64 + j];
                float  ca = care[w * 64 + j];
                float ih = fmaxf(fminf(ry2[r], c4.z) - fmaxf(ry1[r], c4.x), 0.0f);
                float iw = fmaxf(fminf(rx2[r], c4.w) - fmaxf(rx1[r], c4.y), 0.0f);
                float inter = __fmul_rn(ih, iw);
                float dd = __fadd_rn(__fadd_rn(__fadd_rn(rar[r], ca), -inter), 1e-8f);
                bool hit = (__fdiv_rn(inter, dd) > IOU_THR);
                bits[r] = hit ? (bits[r] | (1ull << j)) : (bits[r] & ~(1ull << j));
            }
        }

        #pragma unroll
        for (int r = 0; r < 2; r++) {
            int i = irow[r];
            // C only ever reads words wg >= i>>6; skip the rest
            if (i < PRE_NMS && wg < NW && wg >= (i >> 6)) {
                int dlt = i - wg * 64;     // keep only cols j > i
                u64 m = (dlt < 0) ? ~0ull : ((dlt >= 63) ? 0ull : (~0ull << (dlt + 1)));
                g_masks[b][i][wg] = bits[r] & m;
            }
        }
    }
}

// ================= Kernel C: greedy bit-reduce + output ====================
#define C_NT 512

__global__ __launch_bounds__(C_NT, 1)
void nms_reduce_kernel(float* __restrict__ out)
{
    const int b   = blockIdx.x;
    const int tid = threadIdx.x;

    __shared__ u64 s_diag[64];
    __shared__ u64 s_pub[4];
    __shared__ int s_rows[64];
    __shared__ int s_nk;

    float* ob = out + (size_t)b * POST_NMS * 4;
    float* os = out + (size_t)BATCH * POST_NMS * 4 + (size_t)b * POST_NMS;

    for (int t = tid; t < POST_NMS * 4; t += C_NT) ob[t] = 0.0f;
    for (int t = tid; t < POST_NMS; t += C_NT)     os[t] = 0.0f;

    const int w   = tid >> 2;        // owned word (valid when tid < 376)
    const int sub = tid & 3;
    u64 rem = 0ull;

    if (tid >= 448) s_diag[tid - 448] = g_masks[b][tid - 448][0];
    if (tid < 4) s_pub[tid] = 0ull;
    __syncthreads();

    int cnt = 0;
    for (int c = 0; c < NW; c++) {
        if (tid == 0) {
            u64 remc = s_pub[0] | s_pub[1] | s_pub[2] | s_pub[3];
            int lim = PRE_NMS - c * 64;             // >= 1 (94*64 = 6016 > 6000)
            u64 alive = ~remc;
            if (lim < 64) alive &= ((1ull << lim) - 1ull);
            int nk = 0, cc = cnt;
            while (alive && cc < POST_NMS) {
                int i = __ffsll((long long)alive) - 1;
                s_rows[nk++] = c * 64 + i;
                cc++;
                alive &= ~(s_diag[i] | (1ull << i));
            }
            s_nk = nk;
        }
        __syncthreads();
        const int nk = s_nk;

        if (tid < nk) {
            int r    = s_rows[tid];
            int rank = cnt + tid;
            ob[rank * 4 + 0] = fminf(fmaxf(g_y1[b][r], 0.0f), 1.0f);
            ob[rank * 4 + 1] = fminf(fmaxf(g_x1[b][r], 0.0f), 1.0f);
            ob[rank * 4 + 2] = fminf(fmaxf(g_y2[b][r], 0.0f), 1.0f);
            ob[rank * 4 + 3] = fminf(fmaxf(g_x2[b][r], 0.0f), 1.0f);
            os[rank] = g_sc[b][r];
        }

        if (tid < 376 && w > c) {
            #pragma unroll 4
            for (int m = sub; m < nk; m += 4) rem |= g_masks[b][s_rows[m]][w];
        }

        if (c + 1 < NW && tid >= 448) {
            int row = (c + 1) * 64 + (tid - 448);
            s_diag[tid - 448] = (row < PRE_NMS) ? g_masks[b][row][c + 1] : 0ull;
        }

        if (tid < 376 && w == c + 1) s_pub[sub] = rem;

        cnt += nk;
        __syncthreads();
        if (cnt >= POST_NMS) break;
    }
}

// ============================== launch =====================================
extern "C" void kernel_launch(void* const* d_in, const int* in_sizes, int n_in,
                              void* d_out, int out_size) {
    const float* deltas  = (const float*)d_in[0];  // [16,31,31,36]
    const float* probs   = (const float*)d_in[1];  // [16,31,31,9]
    const float* anchors = (const float*)d_in[2];  // [8649,4]
    float* out = (float*)d_out;

    cudaFuncSetAttribute(sort_decode_kernel,
                         cudaFuncAttributeMaxDynamicSharedMemorySize, A_SMEM_TOTAL);

    sort_decode_kernel<<<BATCH, A_NT, A_SMEM_TOTAL>>>(deltas, probs, anchors);
    iou_matrix_kernel<<<dim3(B_SB, B_SB, BATCH), B_NT>>>();
    nms_reduce_kernel<<<BATCH, C_NT>>>(out);
}

// round 7
// speedup vs baseline: 1.3202x; 1.3202x over previous
#include <cuda_runtime.h>
#include <cuda_bf16.h>
#include <cstdint>

#define IMG_N_ANC   8649      // 31*31*9
#define PRE_NMS     6000
#define POST_NMS    1500
#define IOU_THR     0.7f
#define BATCH       16
#define NW          94        // 94 u64 words cover 6016 >= 6000 cols
#define NWP         96        // padded row stride (768 B)
#define NPAD        6016
#define NBIN        2048
#define NKEY        8704      // padded key capacity (>= 8649)

typedef unsigned long long u64;

// ---------------- device scratch (static; no allocations) ----------------
// row-major masks: g_masks[b][row][word]  (word w holds cols w*64..w*64+63)
__device__ u64   g_masks[BATCH][NPAD][NWP];   // ~73.9 MB
__device__ float g_y1[BATCH][NPAD];
__device__ float g_x1[BATCH][NPAD];
__device__ float g_y2[BATCH][NPAD];
__device__ float g_x2[BATCH][NPAD];
__device__ float g_ar[BATCH][NPAD];
__device__ float g_sc[BATCH][NPAD];

// ================= Kernel A: bucket sort + decode top-6000 =================
// Scores uniform [0,1): value-binned buckets are balanced (avg 4.2/bin).
// Exact ordering: bins monotone in score; within-bin insertion sort on the
// full u64 key (score bits || inverted index) == lax.top_k tie behavior.
#define A_NT          1024
#define A_OFF_RAW     0                              // u64 keys_raw[NKEY]
#define A_OFF_SORT    (NKEY * 8)                     // u64 keys_sorted[NKEY]
#define A_OFF_HIST    (A_OFF_SORT + NKEY * 8)        // u32 hist[NBIN]
#define A_OFF_START   (A_OFF_HIST + NBIN * 4)        // u32 start[NBIN]
#define A_SMEM_TOTAL  (A_OFF_START + NBIN * 4)       // ~155.6 KB

__global__ __launch_bounds__(A_NT, 1)
void sort_decode_kernel(const float* __restrict__ deltas,   // [B,N,4]
                        const float* __restrict__ probs,    // [B,N]
                        const float* __restrict__ anchors)  // [N,4]
{
    extern __shared__ char smem[];
    u64* keys_raw    = (u64*)(smem + A_OFF_RAW);
    u64* keys_sorted = (u64*)(smem + A_OFF_SORT);
    unsigned int* hist  = (unsigned int*)(smem + A_OFF_HIST);
    unsigned int* start = (unsigned int*)(smem + A_OFF_START);

    const int b   = blockIdx.x;
    const int tid = threadIdx.x;
    const int nt  = A_NT;

    for (int i = tid; i < NBIN; i += nt) hist[i] = 0u;
    __syncthreads();

    // pass 1: build keys + value-binned histogram
    const float* pb = probs + (size_t)b * IMG_N_ANC;
    for (int i = tid; i < IMG_N_ANC; i += nt) {
        float s = pb[i];
        unsigned int bits = __float_as_uint(s);       // [0,1): bit order == value order
        u64 k = ((u64)bits << 32) | (u64)(0xFFFFFFFFu - (unsigned)i);
        keys_raw[i] = k;
        int bin = (int)(s * (float)NBIN);
        bin = max(0, min(NBIN - 1, bin));
        atomicAdd(&hist[bin], 1u);
    }
    __syncthreads();

    // descending prefix scan: start[v] = #keys in bins > v  (one warp)
    if (tid < 32) {
        const int lane = tid;
        int part = 0;
        #pragma unroll 8
        for (int q = 0; q < 64; q++) part += (int)hist[NBIN - 1 - (lane * 64 + q)];
        int inc = part;
        #pragma unroll
        for (int off = 1; off < 32; off <<= 1) {
            int v = __shfl_up_sync(0xFFFFFFFFu, inc, off);
            if (lane >= off) inc += v;
        }
        int excl = inc - part;                        // keys in lanes above (higher bins)
        for (int q = 0; q < 64; q++) {
            int v = NBIN - 1 - (lane * 64 + q);
            start[v] = (unsigned int)excl;
            excl += (int)hist[v];
        }
    }
    __syncthreads();

    // reset hist -> per-bin scatter counters
    for (int i = tid; i < NBIN; i += nt) hist[i] = 0u;
    __syncthreads();

    // pass 2: scatter keys to bin segments
    for (int i = tid; i < IMG_N_ANC; i += nt) {
        u64 k = keys_raw[i];
        float s = __uint_as_float((unsigned int)(k >> 32));
        int bin = (int)(s * (float)NBIN);
        bin = max(0, min(NBIN - 1, bin));
        unsigned int pos = start[bin] + atomicAdd(&hist[bin], 1u);
        keys_sorted[pos] = k;
    }
    __syncthreads();

    // pass 3: per-bin insertion sort (descending, exact u64 keys)
    for (int v = tid; v < NBIN; v += nt) {
        int s0 = (int)start[v];
        int c  = (int)hist[v];
        if (s0 < PRE_NMS && c > 1) {
            for (int a = s0 + 1; a < s0 + c; a++) {
                u64 key = keys_sorted[a];
                int p = a - 1;
                while (p >= s0 && keys_sorted[p] < key) {
                    keys_sorted[p + 1] = keys_sorted[p];
                    p--;
                }
                keys_sorted[p + 1] = key;
            }
        }
    }
    __syncthreads();

    // pass 4: decode top-6000 to global SoA
    const float* db = deltas + (size_t)b * IMG_N_ANC * 4;
    for (int t = tid; t < PRE_NMS; t += nt) {
        u64 key = keys_sorted[t];
        unsigned int idx = 0xFFFFFFFFu - (unsigned int)(key & 0xFFFFFFFFull);
        float score = __uint_as_float((unsigned int)(key >> 32));

        float a0 = anchors[idx * 4 + 0];
        float a1 = anchors[idx * 4 + 1];
        float a2 = anchors[idx * 4 + 2];
        float a3 = anchors[idx * 4 + 3];
        float d0 = db[(size_t)idx * 4 + 0] * 0.1f;
        float d1 = db[(size_t)idx * 4 + 1] * 0.1f;
        float d2 = db[(size_t)idx * 4 + 2] * 0.2f;
        float d3 = db[(size_t)idx * 4 + 3] * 0.2f;

        float anc_h = a2 - a0;
        float anc_w = a3 - a1;
        float ctr_y = a0 + 0.5f * anc_h;
        float ctr_x = a1 + 0.5f * anc_w;
        float bh = expf(d2) * anc_h;
        float bw = expf(d3) * anc_w;
        float bcy = d0 * anc_h + ctr_y;
        float bcx = d1 * anc_w + ctr_x;
        float y1 = bcy - 0.5f * bh;
        float x1 = bcx - 0.5f * bw;
        float y2 = y1 + bh;
        float x2 = x1 + bw;

        g_y1[b][t] = y1; g_x1[b][t] = x1;
        g_y2[b][t] = y2; g_x2[b][t] = x2;
        g_ar[b][t] = (y2 - y1) * (x2 - x1);
        g_sc[b][t] = score;
    }
}

// ================= Kernel B: forward suppression bit-matrix =================
// (round-5 version — proven fastest)  grid = (94, 24, 16), 64 threads,
// each thread owns 4 rows.
__global__ __launch_bounds__(64)
void iou_matrix_kernel()
{
    const int cb = blockIdx.x;
    const int rb = blockIdx.y;
    if (cb < rb * 4) return;
    const int b   = blockIdx.z;
    const int tid = threadIdx.x;

    __shared__ float4 cbox[64];
    __shared__ float  care[64];

    const int j0 = cb * 64;
    {
        int j = j0 + tid;
        if (j < PRE_NMS) {
            cbox[tid] = make_float4(g_y1[b][j], g_x1[b][j], g_y2[b][j], g_x2[b][j]);
            care[tid] = g_ar[b][j];
        } else {
            cbox[tid] = make_float4(0.f, 0.f, 0.f, 0.f);   // inter=0 -> never hits
            care[tid] = 0.f;
        }
    }
    __syncthreads();

    float ry1[4], rx1[4], ry2[4], rx2[4], rar[4];
    u64 bits[4] = {0ull, 0ull, 0ull, 0ull};
    int  irow[4];
    #pragma unroll
    for (int r = 0; r < 4; r++) {
        int i = rb * 256 + r * 64 + tid;
        irow[r] = i;
        int ii = (i < PRE_NMS) ? i : 0;
        ry1[r] = g_y1[b][ii]; rx1[r] = g_x1[b][ii];
        ry2[r] = g_y2[b][ii]; rx2[r] = g_x2[b][ii];
        rar[r] = g_ar[b][ii];
    }

    #pragma unroll 8
    for (int j = 0; j < 64; j++) {
        float4 c4 = cbox[j];
        float  ca = care[j];
        #pragma unroll
        for (int r = 0; r < 4; r++) {
            float ih = fmaxf(fminf(ry2[r], c4.z) - fmaxf(ry1[r], c4.x), 0.0f);
            float iw = fmaxf(fminf(rx2[r], c4.w) - fmaxf(rx1[r], c4.y), 0.0f);
            float inter = ih * iw;
            float d = rar[r] + ca - inter + 1e-8f;   // exact reference op order
            float diff = fmaf(-IOU_THR, d, inter);   // inter - 0.7*d
            bool hit = diff > 0.0f;
            if (fabsf(diff) <= 1e-5f * d)            // rare: exact IEEE decision
                hit = (inter / d) > IOU_THR;
            if (hit) bits[r] |= (1ull << j);
        }
    }

    #pragma unroll
    for (int r = 0; r < 4; r++) {
        int i = irow[r];
        if (i < PRE_NMS) {
            int dlt = i - j0;   // keep only cols j > i
            u64 m = (dlt < 0) ? ~0ull : ((dlt >= 63) ? 0ull : (~0ull << (dlt + 1)));
            g_masks[b][i][cb] = bits[r] & m;
        }
    }
}

// ================= Kernel C: greedy bit-reduce + output ====================
// (round-5 version — proven) 512 threads; 4-way co-owned suppression words.
#define C_NT 512

__global__ __launch_bounds__(C_NT, 1)
void nms_reduce_kernel(float* __restrict__ out)
{
    const int b   = blockIdx.x;
    const int tid = threadIdx.x;

    __shared__ u64 s_diag[64];
    __shared__ u64 s_pub[4];
    __shared__ int s_rows[64];
    __shared__ int s_nk;

    float* ob = out + (size_t)b * POST_NMS * 4;
    float* os = out + (size_t)BATCH * POST_NMS * 4 + (size_t)b * POST_NMS;

    for (int t = tid; t < POST_NMS * 4; t += C_NT) ob[t] = 0.0f;
    for (int t = tid; t < POST_NMS; t += C_NT)     os[t] = 0.0f;

    const int w   = tid >> 2;        // owned word (valid when tid < 376)
    const int sub = tid & 3;
    u64 rem = 0ull;

    if (tid >= 448) s_diag[tid - 448] = g_masks[b][tid - 448][0];
    if (tid < 4) s_pub[tid] = 0ull;
    __syncthreads();

    int cnt = 0;
    for (int c = 0; c < NW; c++) {
        if (tid == 0) {
            u64 remc = s_pub[0] | s_pub[1] | s_pub[2] | s_pub[3];
            int lim = PRE_NMS - c * 64;             // >= 1 (94*64 = 6016 > 6000)
            u64 alive = ~remc;
            if (lim < 64) alive &= ((1ull << lim) - 1ull);
            int nk = 0, cc = cnt;
            while (alive && cc < POST_NMS) {
                int i = __ffsll((long long)alive) - 1;
                s_rows[nk++] = c * 64 + i;
                cc++;
                alive &= ~(s_diag[i] | (1ull << i));
            }
            s_nk = nk;
        }
        __syncthreads();
        const int nk = s_nk;

        if (tid < nk) {
            int r    = s_rows[tid];
            int rank = cnt + tid;
            ob[rank * 4 + 0] = fminf(fmaxf(g_y1[b][r], 0.0f), 1.0f);
            ob[rank * 4 + 1] = fminf(fmaxf(g_x1[b][r], 0.0f), 1.0f);
            ob[rank * 4 + 2] = fminf(fmaxf(g_y2[b][r], 0.0f), 1.0f);
            ob[rank * 4 + 3] = fminf(fmaxf(g_x2[b][r], 0.0f), 1.0f);
            os[rank] = g_sc[b][r];
        }

        if (tid < 376 && w > c) {
            #pragma unroll 4
            for (int m = sub; m < nk; m += 4) rem |= g_masks[b][s_rows[m]][w];
        }

        if (c + 1 < NW && tid >= 448) {
            int row = (c + 1) * 64 + (tid - 448);
            s_diag[tid - 448] = (row < PRE_NMS) ? g_masks[b][row][c + 1] : 0ull;
        }

        if (tid < 376 && w == c + 1) s_pub[sub] = rem;

        cnt += nk;
        __syncthreads();
        if (cnt >= POST_NMS) break;
    }
}

// ============================== launch =====================================
extern "C" void kernel_launch(void* const* d_in, const int* in_sizes, int n_in,
                              void* d_out, int out_size) {
    const float* deltas  = (const float*)d_in[0];  // [16,31,31,36]
    const float* probs   = (const float*)d_in[1];  // [16,31,31,9]
    const float* anchors = (const float*)d_in[2];  // [8649,4]
    float* out = (float*)d_out;

    cudaFuncSetAttribute(sort_decode_kernel,
                         cudaFuncAttributeMaxDynamicSharedMemorySize, A_SMEM_TOTAL);

    sort_decode_kernel<<<BATCH, A_NT, A_SMEM_TOTAL>>>(deltas, probs, anchors);
    iou_matrix_kernel<<<dim3(NW, 24, BATCH), 64>>>();
    nms_reduce_kernel<<<BATCH, C_NT>>>(out);
}